// round 1
// baseline (speedup 1.0000x reference)
#include <cuda_runtime.h>
#include <cuda_bf16.h>
#include <stdint.h>

#define N_ROWS 65536
#define DIM    512

// Scratch (alloc-free rule: __device__ globals)
__device__ __nv_bfloat16 g_Db[(size_t)N_ROWS * DIM];   // bf16(delta), 64 MB
__device__ __nv_bfloat16 g_Rb[DIM * DIM];              // bf16(S_inv - I), 512 KB

// ---------------------------------------------------------------------------
// Kernel A: delta = x - x_fit (fp32); out[n] = ||delta||^2 (exact fp32);
//           g_Db = bf16(delta)
// One warp per row. float4 loads -> fully coalesced.
// ---------------------------------------------------------------------------
__global__ void prep_delta(const float* __restrict__ x,
                           const float* __restrict__ xf,
                           float* __restrict__ out) {
    int warp = (blockIdx.x * blockDim.x + threadIdx.x) >> 5;
    int lane = threadIdx.x & 31;
    if (warp >= N_ROWS) return;
    const float4* xr = (const float4*)(x  + (size_t)warp * DIM);
    const float4* fr = (const float4*)(xf + (size_t)warp * DIM);
    uint2* db = (uint2*)(g_Db + (size_t)warp * DIM);
    float ss = 0.f;
#pragma unroll
    for (int j = 0; j < 4; j++) {
        int idx = lane + 32 * j;            // covers 512/4 = 128 float4 per row
        float4 a = xr[idx], b = fr[idx];
        float d0 = a.x - b.x, d1 = a.y - b.y, d2 = a.z - b.z, d3 = a.w - b.w;
        ss += d0 * d0 + d1 * d1 + d2 * d2 + d3 * d3;
        __nv_bfloat162 p0 = __floats2bfloat162_rn(d0, d1);
        __nv_bfloat162 p1 = __floats2bfloat162_rn(d2, d3);
        uint2 v;
        v.x = *(uint32_t*)&p0;
        v.y = *(uint32_t*)&p1;
        db[idx] = v;
    }
#pragma unroll
    for (int o = 16; o; o >>= 1) ss += __shfl_xor_sync(0xffffffffu, ss, o);
    if (lane == 0) out[warp] = ss;
}

// ---------------------------------------------------------------------------
// Kernel B: g_Rb = bf16(S_inv - I)
// ---------------------------------------------------------------------------
__global__ void prep_R(const float* __restrict__ S) {
    int i = blockIdx.x * blockDim.x + threadIdx.x;
    if (i >= DIM * DIM) return;
    int r = i >> 9, c = i & 511;
    float v = S[i] - (r == c ? 1.0f : 0.0f);
    g_Rb[i] = __float2bfloat16(v);
}

// ---------------------------------------------------------------------------
// Kernel C: out[n] += sum_e Db[n,e] * (Db @ Rb)[n,e]
// Block: 128 rows. Loop over 4 e-tiles of 128; k-tiled (64) smem GEMM with
// mma.sync.m16n8k16 bf16->f32. R is symmetric -> B fragments read as Rb[e][k]
// (contiguous along k, no transpose needed). Fused epilogue: Y * delta,
// reduce along e into per-row shared accumulators. Deterministic, no gmem
// atomics.
// ---------------------------------------------------------------------------
#define MT 128
#define NT 128
#define KT 64
#define AP 72      // padded bf16 stride for A/B tiles (conflict-free frag LDS)
#define DP 132     // padded bf16 stride for epilogue delta tile

#define AB_BYTES ((MT * AP + NT * AP) * 2)   // 36864
#define DE_BYTES (MT * DP * 2)               // 33792

__global__ __launch_bounds__(256, 1) void mahal_gemm(float* __restrict__ out) {
    __shared__ __align__(16) unsigned char smbuf[AB_BYTES];  // De aliases A/B
    __shared__ float rowacc[MT];

    typedef __nv_bfloat16 RowA[AP];
    typedef __nv_bfloat16 RowD[DP];
    RowA* As = (RowA*)smbuf;
    RowA* Bs = (RowA*)(smbuf + MT * AP * 2);
    RowD* De = (RowD*)smbuf;

    const int tid  = threadIdx.x;
    const int lane = tid & 31, warp = tid >> 5;
    const int wm = warp & 3;   // m quadrant: rows [32*wm, 32*wm+32)
    const int we = warp >> 2;  // e half:    cols [64*we, 64*we+64)
    const int gid = lane >> 2, tig = lane & 3;
    const int rowbase = blockIdx.x * MT;

    if (tid < MT) rowacc[tid] = 0.f;

    for (int et = 0; et < DIM / NT; et++) {
        float c[2][8][4];
#pragma unroll
        for (int i = 0; i < 2; i++)
#pragma unroll
            for (int j = 0; j < 8; j++)
#pragma unroll
                for (int q = 0; q < 4; q++) c[i][j][q] = 0.f;

        for (int kt = 0; kt < DIM / KT; kt++) {
            __syncthreads();   // protect A/B (and aliased De) from prior reads
            // Load A tile: Db[rowbase + r][kt*64 + k]  (128x64 bf16)
#pragma unroll
            for (int i = 0; i < 8; i++) {
                int idx = tid + 256 * i;       // 2048 uint2
                int r = idx >> 4;              // 16 uint2 per row
                int cc = (idx & 15) * 4;
                uint2 v = *(const uint2*)(g_Db + (size_t)(rowbase + r) * DIM + kt * KT + cc);
                *(uint2*)&As[r][cc] = v;
            }
            // Load B tile: Rb[et*128 + e][kt*64 + k]  (symmetric R)
#pragma unroll
            for (int i = 0; i < 8; i++) {
                int idx = tid + 256 * i;
                int r = idx >> 4;
                int cc = (idx & 15) * 4;
                uint2 v = *(const uint2*)(g_Rb + (size_t)(et * NT + r) * DIM + kt * KT + cc);
                *(uint2*)&Bs[r][cc] = v;
            }
            __syncthreads();

#pragma unroll
            for (int kk = 0; kk < 4; kk++) {
                uint32_t a[2][4], b[8][2];
#pragma unroll
                for (int mi = 0; mi < 2; mi++) {
                    int r = wm * 32 + mi * 16 + gid;
                    a[mi][0] = *(const uint32_t*)&As[r][kk * 16 + tig * 2];
                    a[mi][1] = *(const uint32_t*)&As[r + 8][kk * 16 + tig * 2];
                    a[mi][2] = *(const uint32_t*)&As[r][kk * 16 + 8 + tig * 2];
                    a[mi][3] = *(const uint32_t*)&As[r + 8][kk * 16 + 8 + tig * 2];
                }
#pragma unroll
                for (int nf = 0; nf < 8; nf++) {
                    int e = we * 64 + nf * 8 + gid;
                    b[nf][0] = *(const uint32_t*)&Bs[e][kk * 16 + tig * 2];
                    b[nf][1] = *(const uint32_t*)&Bs[e][kk * 16 + 8 + tig * 2];
                }
#pragma unroll
                for (int mi = 0; mi < 2; mi++)
#pragma unroll
                    for (int nf = 0; nf < 8; nf++)
                        asm volatile(
                            "mma.sync.aligned.m16n8k16.row.col.f32.bf16.bf16.f32 "
                            "{%0,%1,%2,%3}, {%4,%5,%6,%7}, {%8,%9}, {%0,%1,%2,%3};"
                            : "+f"(c[mi][nf][0]), "+f"(c[mi][nf][1]),
                              "+f"(c[mi][nf][2]), "+f"(c[mi][nf][3])
                            : "r"(a[mi][0]), "r"(a[mi][1]), "r"(a[mi][2]), "r"(a[mi][3]),
                              "r"(b[nf][0]), "r"(b[nf][1]));
            }
        }

        __syncthreads();
        // Epilogue delta tile: Db[rowbase + r][et*128 + e]  (128x128 bf16)
#pragma unroll
        for (int i = 0; i < 16; i++) {
            int idx = tid + 256 * i;     // 4096 uint2
            int r = idx >> 5;            // 32 uint2 per row
            int cc = (idx & 31) * 4;
            uint2 v = *(const uint2*)(g_Db + (size_t)(rowbase + r) * DIM + et * NT + cc);
            *(uint2*)&De[r][cc] = v;
        }
        __syncthreads();

        float p[4] = {0.f, 0.f, 0.f, 0.f};  // rows wm*32 + {gid, gid+8, gid+16, gid+24}
#pragma unroll
        for (int mi = 0; mi < 2; mi++) {
            int r0 = wm * 32 + mi * 16 + gid;
#pragma unroll
            for (int nf = 0; nf < 8; nf++) {
                int e = we * 64 + nf * 8 + tig * 2;
                float d00 = __bfloat162float(De[r0][e]);
                float d01 = __bfloat162float(De[r0][e + 1]);
                float d10 = __bfloat162float(De[r0 + 8][e]);
                float d11 = __bfloat162float(De[r0 + 8][e + 1]);
                p[mi * 2 + 0] += c[mi][nf][0] * d00 + c[mi][nf][1] * d01;
                p[mi * 2 + 1] += c[mi][nf][2] * d10 + c[mi][nf][3] * d11;
            }
        }
        atomicAdd(&rowacc[wm * 32 + gid],      p[0]);
        atomicAdd(&rowacc[wm * 32 + gid + 8],  p[1]);
        atomicAdd(&rowacc[wm * 32 + gid + 16], p[2]);
        atomicAdd(&rowacc[wm * 32 + gid + 24], p[3]);
    }

    __syncthreads();
    if (tid < MT) out[rowbase + tid] += rowacc[tid];
}

// ---------------------------------------------------------------------------
extern "C" void kernel_launch(void* const* d_in, const int* in_sizes, int n_in,
                              void* d_out, int out_size) {
    const float* x  = (const float*)d_in[0];
    const float* xf = (const float*)d_in[1];
    const float* S  = (const float*)d_in[2];
    float* out = (float*)d_out;

    prep_delta<<<N_ROWS / 8, 256>>>(x, xf, out);       // 8 warps/block
    prep_R<<<(DIM * DIM) / 256, 256>>>(S);
    mahal_gemm<<<N_ROWS / MT, 256>>>(out);
}

// round 4
// speedup vs baseline: 1.4471x; 1.4471x over previous
#include <cuda_runtime.h>
#include <cuda_bf16.h>
#include <stdint.h>

#define N_ROWS 65536
#define DIM    512
#define MT     128

// bf16(S_inv - I), 512 KB, L2-resident
__device__ __nv_bfloat16 g_Rb[DIM * DIM];

// ---- dynamic smem layout (bytes) ----
#define AS    520                          // A tile stride (bf16 elems), 1040B rows
#define BSTR  136                          // B tile stride (bf16 elems), 272B rows
#define SM_A   0                           // 128 x AS bf16 = 133120
#define SM_B0  133120                      // 128 x BSTR bf16 = 34816
#define SM_B1  167936
#define SM_RSS 202752                      // 128 f32 ||delta||^2
#define SM_RC  203264                      // 128 f32 correction accum
#define SM_TOTAL 203776

__device__ __forceinline__ uint32_t s2u(const void* p) {
    uint32_t a;
    asm("{ .reg .u64 t; cvta.to.shared.u64 t, %1; cvt.u32.u64 %0, t; }" : "=r"(a) : "l"(p));
    return a;
}

// ---------------------------------------------------------------------------
__global__ void prep_R(const float* __restrict__ S) {
    int i = blockIdx.x * blockDim.x + threadIdx.x;
    if (i >= DIM * DIM) return;
    int r = i >> 9, c = i & 511;
    g_Rb[i] = __float2bfloat16(S[i] - (r == c ? 1.0f : 0.0f));
}

// ---------------------------------------------------------------------------
// Fused: per CTA (256 thr) of 128 rows:
//  stage1: delta = x - xf (fp32), ||delta||^2 exact, bf16 delta -> SMEM A tile
//  gemm:   C[128,512] = A @ R via mma.sync m16n8k16 bf16, B tiles (g_Rb)
//          cp.async double-buffered; warp (wm,we) owns 32 rows x 64 cols
//  epi:    per e-tile, corr += C .* delta (delta re-read from SMEM A)
//  out[n] = ||delta_n||^2 + corr_n
// ---------------------------------------------------------------------------
__global__ void __launch_bounds__(256, 1) mahal_fused(const float* __restrict__ x,
                                                      const float* __restrict__ xf,
                                                      float* __restrict__ out) {
    extern __shared__ __align__(1024) unsigned char sm[];
    const uint32_t sb = s2u(sm);
    const int tid = threadIdx.x, lane = tid & 31, w = tid >> 5;
    const int wm = w & 3;          // row quadrant (32 rows)
    const int we = w >> 2;         // col half (64 cols within 128-wide e-tile)
    const int gid = lane >> 2, tig = lane & 3;
    const int rowbase = blockIdx.x * MT;

    if (tid < MT) *(float*)(sm + SM_RC + tid * 4) = 0.f;

    // ---- issue B chunk CH into buffer BUF (runtime values ok) ----
#define ISSUE_B(CH, BUF)                                                               \
    {                                                                                  \
        const int et_ = (CH) >> 2, kt_ = (CH) & 3;                                     \
        _Pragma("unroll")                                                              \
        for (int j = 0; j < 8; j++) {                                                  \
            int idx = tid + 256 * j;                                                   \
            int er = idx >> 4, cc = idx & 15;                                          \
            uint32_t dst = sb + ((BUF) ? SM_B1 : SM_B0) + er * (BSTR * 2) + cc * 16;   \
            const void* src = (const char*)g_Rb +                                      \
                ((size_t)(et_ * 128 + er) * DIM + kt_ * 128 + cc * 8) * 2;             \
            asm volatile("cp.async.cg.shared.global [%0], [%1], 16;"                   \
                         :: "r"(dst), "l"(src));                                       \
        }                                                                              \
    }

    // prefetch chunks 0,1 before stage-1 so they overlap the fp32 streaming
    ISSUE_B(0, 0)
    asm volatile("cp.async.commit_group;" ::: "memory");
    ISSUE_B(1, 1)
    asm volatile("cp.async.commit_group;" ::: "memory");

    // ---- stage 1: warp w handles rows w, w+8, ..., w+120 ----
    {
        const float4* x4  = (const float4*)x;
        const float4* f4  = (const float4*)xf;
#pragma unroll 2
        for (int t = 0; t < 16; t++) {
            int row = w + 8 * t;
            const float4* xr = x4 + (size_t)(rowbase + row) * 128;
            const float4* fr = f4 + (size_t)(rowbase + row) * 128;
            float s = 0.f;
#pragma unroll
            for (int j = 0; j < 4; j++) {
                int ci = lane + 32 * j;
                float4 a = xr[ci], b = fr[ci];
                float d0 = a.x - b.x, d1 = a.y - b.y, d2 = a.z - b.z, d3 = a.w - b.w;
                s += d0 * d0 + d1 * d1 + d2 * d2 + d3 * d3;
                __nv_bfloat162 p0 = __floats2bfloat162_rn(d0, d1);
                __nv_bfloat162 p1 = __floats2bfloat162_rn(d2, d3);
                uint2 v; v.x = *(uint32_t*)&p0; v.y = *(uint32_t*)&p1;
                *(uint2*)(sm + SM_A + row * (AS * 2) + ci * 8) = v;
            }
#pragma unroll
            for (int o = 16; o; o >>= 1) s += __shfl_xor_sync(0xffffffffu, s, o);
            if (lane == 0) *(float*)(sm + SM_RSS + row * 4) = s;
        }
    }

    // ---- per-thread ldmatrix address offsets ----
    const int a_row = (lane & 7) + ((lane >> 3) & 1) * 8;   // within 16-row block
    const int a_kb  = (lane >> 4) * 16;                     // k byte offset
    const int b_row = (lane & 7) + ((lane >> 4) & 1) * 8;   // within 16-n block
    const int b_kb  = ((lane >> 3) & 1) * 16;

    const uint32_t a_base = sb + SM_A + (wm * 32 + a_row) * (AS * 2) + a_kb;
    float p[4] = {0.f, 0.f, 0.f, 0.f};                      // corr partials, persist over et
    float c[2][8][4];
#pragma unroll
    for (int mi = 0; mi < 2; mi++)
#pragma unroll
        for (int nf = 0; nf < 8; nf++)
#pragma unroll
            for (int q = 0; q < 4; q++) c[mi][nf][q] = 0.f;

    for (int i = 0; i < 16; i++) {
        const int buf = i & 1, kt = i & 3;
        asm volatile("cp.async.wait_group 1;" ::: "memory");
        __syncthreads();

        const uint32_t bbase = sb + (buf ? SM_B1 : SM_B0) + (we * 64 + b_row) * (BSTR * 2) + b_kb;
        const uint32_t akt = a_base + kt * 256;
#pragma unroll
        for (int kk = 0; kk < 8; kk++) {
            uint32_t a[2][4], b[8][2];
#pragma unroll
            for (int mi = 0; mi < 2; mi++) {
                uint32_t addr = akt + mi * 16 * (AS * 2) + kk * 32;
                asm volatile("ldmatrix.sync.aligned.m8n8.x4.shared.b16 {%0,%1,%2,%3}, [%4];"
                             : "=r"(a[mi][0]), "=r"(a[mi][1]), "=r"(a[mi][2]), "=r"(a[mi][3])
                             : "r"(addr));
            }
#pragma unroll
            for (int pq = 0; pq < 4; pq++) {
                uint32_t addr = bbase + pq * 16 * (BSTR * 2) + kk * 32;
                asm volatile("ldmatrix.sync.aligned.m8n8.x4.shared.b16 {%0,%1,%2,%3}, [%4];"
                             : "=r"(b[2 * pq][0]), "=r"(b[2 * pq][1]),
                               "=r"(b[2 * pq + 1][0]), "=r"(b[2 * pq + 1][1])
                             : "r"(addr));
            }
#pragma unroll
            for (int mi = 0; mi < 2; mi++)
#pragma unroll
                for (int nf = 0; nf < 8; nf++)
                    asm volatile(
                        "mma.sync.aligned.m16n8k16.row.col.f32.bf16.bf16.f32 "
                        "{%0,%1,%2,%3}, {%4,%5,%6,%7}, {%8,%9}, {%0,%1,%2,%3};"
                        : "+f"(c[mi][nf][0]), "+f"(c[mi][nf][1]),
                          "+f"(c[mi][nf][2]), "+f"(c[mi][nf][3])
                        : "r"(a[mi][0]), "r"(a[mi][1]), "r"(a[mi][2]), "r"(a[mi][3]),
                          "r"(b[nf][0]), "r"(b[nf][1]));
        }
        __syncthreads();
        if (i + 2 < 16) ISSUE_B(i + 2, buf)
        asm volatile("cp.async.commit_group;" ::: "memory");

        if ((i & 3) == 3) {
            // epilogue for e-tile et = i>>2: corr += C .* delta
            const int et = i >> 2;
#pragma unroll
            for (int mi = 0; mi < 2; mi++) {
                int r0 = wm * 32 + mi * 16 + gid;
#pragma unroll
                for (int nf = 0; nf < 8; nf++) {
                    int e = et * 128 + we * 64 + nf * 8 + tig * 2;
                    uint32_t v0 = *(const uint32_t*)(sm + SM_A + r0 * (AS * 2) + e * 2);
                    uint32_t v1 = *(const uint32_t*)(sm + SM_A + (r0 + 8) * (AS * 2) + e * 2);
                    float2 f0 = __bfloat1622float2(*(__nv_bfloat162*)&v0);
                    float2 f1 = __bfloat1622float2(*(__nv_bfloat162*)&v1);
                    p[mi * 2 + 0] += c[mi][nf][0] * f0.x + c[mi][nf][1] * f0.y;
                    p[mi * 2 + 1] += c[mi][nf][2] * f1.x + c[mi][nf][3] * f1.y;
                    c[mi][nf][0] = c[mi][nf][1] = c[mi][nf][2] = c[mi][nf][3] = 0.f;
                }
            }
        }
    }

    // combine the two we-halves per row
    atomicAdd((float*)(sm + SM_RC + (wm * 32 + gid) * 4),      p[0]);
    atomicAdd((float*)(sm + SM_RC + (wm * 32 + gid + 8) * 4),  p[1]);
    atomicAdd((float*)(sm + SM_RC + (wm * 32 + gid + 16) * 4), p[2]);
    atomicAdd((float*)(sm + SM_RC + (wm * 32 + gid + 24) * 4), p[3]);
    __syncthreads();

    if (tid < MT)
        out[rowbase + tid] = *(const float*)(sm + SM_RSS + tid * 4) +
                             *(const float*)(sm + SM_RC + tid * 4);
}

// ---------------------------------------------------------------------------
extern "C" void kernel_launch(void* const* d_in, const int* in_sizes, int n_in,
                              void* d_out, int out_size) {
    const float* x  = (const float*)d_in[0];
    const float* xf = (const float*)d_in[1];
    const float* S  = (const float*)d_in[2];
    float* out = (float*)d_out;

    cudaFuncSetAttribute(mahal_fused, cudaFuncAttributeMaxDynamicSharedMemorySize, SM_TOTAL);

    prep_R<<<(DIM * DIM) / 256, 256>>>(S);
    mahal_fused<<<N_ROWS / MT, 256, SM_TOTAL>>>(x, xf, out);
}

// round 8
// speedup vs baseline: 1.6088x; 1.1118x over previous
#include <cuda_runtime.h>
#include <cuda_bf16.h>
#include <stdint.h>

#define N_ROWS 65536
#define DIM    512
#define MT     64

// bf16(S_inv - I), 512 KB, L2-resident
__device__ __nv_bfloat16 g_Rb[DIM * DIM];

// ---- dynamic smem layout (bytes) ----
#define AS    520                          // A tile stride (bf16), 1040B rows (==16 mod 128)
#define BSTR  72                           // B chunk stride (bf16), 144B rows (==16 mod 128)
#define SM_A    0                          // 64 x AS bf16  = 66560
#define SM_B0   66560                      // 128 x BSTR bf16 = 18432
#define SM_B1   84992
#define SM_RSS  103424                     // 64 f32 ||delta||^2
#define SM_RC   103680                     // 64 f32 correction accum
#define SM_TOTAL 103936                    // x2 CTAs = 207872 <= 228KB/SM

__device__ __forceinline__ uint32_t s2u(const void* p) {
    uint32_t a;
    asm("{ .reg .u64 t; cvta.to.shared.u64 t, %1; cvt.u32.u64 %0, t; }" : "=r"(a) : "l"(p));
    return a;
}

// ---------------------------------------------------------------------------
__global__ void prep_R(const float* __restrict__ S) {
    int i = blockIdx.x * blockDim.x + threadIdx.x;
    if (i >= DIM * DIM) return;
    int r = i >> 9, c = i & 511;
    g_Rb[i] = __float2bfloat16(S[i] - (r == c ? 1.0f : 0.0f));
}

// ---------------------------------------------------------------------------
// Fused, 2 CTAs/SM: per CTA (256 thr) of 64 rows:
//  stage1: delta = x - xf (fp32), ||delta||^2 exact, bf16 delta -> SMEM A tile
//  gemm:   C[64,512] = A @ R via mma.sync m16n8k16; B chunks (128e x 64k) of
//          g_Rb cp.async double-buffered; warp (wm,we) owns 32 rows x 32 cols
//  epi:    after each e-tile (kt==7), corr += C .* delta; C reset
//  out[n] = ||delta_n||^2 + corr_n
// ---------------------------------------------------------------------------
__global__ void __launch_bounds__(256, 2) mahal_fused(const float* __restrict__ x,
                                                      const float* __restrict__ xf,
                                                      float* __restrict__ out) {
    extern __shared__ __align__(1024) unsigned char sm[];
    const uint32_t sb = s2u(sm);
    const int tid = threadIdx.x, lane = tid & 31, w = tid >> 5;
    const int wm = w & 1;          // row half (32 rows)
    const int we = w >> 1;         // col quarter (32 cols within 128-wide e-tile)
    const int gid = lane >> 2, tig = lane & 3;
    const int rowbase = blockIdx.x * MT;

    if (tid < MT) *(float*)(sm + SM_RC + tid * 4) = 0.f;

    // ---- issue B chunk CH (et = CH>>3, kt = CH&7) into buffer BUF ----
#define ISSUE_B(CH, BUF)                                                               \
    {                                                                                  \
        const int et_ = (CH) >> 3, kt_ = (CH) & 7;                                     \
        _Pragma("unroll")                                                              \
        for (int j = 0; j < 4; j++) {                                                  \
            int idx = tid + 256 * j;                                                   \
            int er = idx >> 3, cc = idx & 7;                                           \
            uint32_t dst = sb + ((BUF) ? SM_B1 : SM_B0) + er * (BSTR * 2) + cc * 16;   \
            const void* src = (const char*)g_Rb +                                      \
                ((size_t)(et_ * 128 + er) * DIM + kt_ * 64 + cc * 8) * 2;              \
            asm volatile("cp.async.cg.shared.global [%0], [%1], 16;"                   \
                         :: "r"(dst), "l"(src));                                       \
        }                                                                              \
    }

    // prefetch chunks 0,1 so they overlap the fp32 streaming
    ISSUE_B(0, 0)
    asm volatile("cp.async.commit_group;" ::: "memory");
    ISSUE_B(1, 1)
    asm volatile("cp.async.commit_group;" ::: "memory");

    // ---- stage 1: warp w handles rows w, w+8, ..., w+56 ----
    {
        const float4* x4  = (const float4*)x;
        const float4* f4  = (const float4*)xf;
#pragma unroll 2
        for (int t = 0; t < 8; t++) {
            int row = w + 8 * t;
            const float4* xr = x4 + (size_t)(rowbase + row) * 128;
            const float4* fr = f4 + (size_t)(rowbase + row) * 128;
            float s = 0.f;
#pragma unroll
            for (int j = 0; j < 4; j++) {
                int ci = lane + 32 * j;
                float4 a = xr[ci], b = fr[ci];
                float d0 = a.x - b.x, d1 = a.y - b.y, d2 = a.z - b.z, d3 = a.w - b.w;
                s += d0 * d0 + d1 * d1 + d2 * d2 + d3 * d3;
                __nv_bfloat162 p0 = __floats2bfloat162_rn(d0, d1);
                __nv_bfloat162 p1 = __floats2bfloat162_rn(d2, d3);
                uint2 v; v.x = *(uint32_t*)&p0; v.y = *(uint32_t*)&p1;
                *(uint2*)(sm + SM_A + row * (AS * 2) + ci * 8) = v;
            }
#pragma unroll
            for (int o = 16; o; o >>= 1) s += __shfl_xor_sync(0xffffffffu, s, o);
            if (lane == 0) *(float*)(sm + SM_RSS + row * 4) = s;
        }
    }

    // ---- per-thread ldmatrix address offsets ----
    const int a_row = (lane & 7) + ((lane >> 3) & 1) * 8;   // within 16-row block
    const int a_kb  = (lane >> 4) * 16;                     // k byte offset
    const int b_row = (lane & 7) + ((lane >> 4) & 1) * 8;   // within 16-n block
    const int b_kb  = ((lane >> 3) & 1) * 16;

    const uint32_t a_base = sb + SM_A + (wm * 32 + a_row) * (AS * 2) + a_kb;
    float p[4] = {0.f, 0.f, 0.f, 0.f};                      // corr partials, persist
    float c[2][4][4];
#pragma unroll
    for (int mi = 0; mi < 2; mi++)
#pragma unroll
        for (int nf = 0; nf < 4; nf++)
#pragma unroll
            for (int q = 0; q < 4; q++) c[mi][nf][q] = 0.f;

    for (int i = 0; i < 32; i++) {
        const int buf = i & 1, kt = i & 7;
        asm volatile("cp.async.wait_group 1;" ::: "memory");
        __syncthreads();

        const uint32_t bbase = sb + (buf ? SM_B1 : SM_B0) + (we * 32 + b_row) * (BSTR * 2) + b_kb;
        const uint32_t akt = a_base + kt * 128;             // 64 bf16 per k-tile
#pragma unroll
        for (int kk = 0; kk < 4; kk++) {
            uint32_t a[2][4], b[4][2];
#pragma unroll
            for (int mi = 0; mi < 2; mi++) {
                uint32_t addr = akt + mi * 16 * (AS * 2) + kk * 32;
                asm volatile("ldmatrix.sync.aligned.m8n8.x4.shared.b16 {%0,%1,%2,%3}, [%4];"
                             : "=r"(a[mi][0]), "=r"(a[mi][1]), "=r"(a[mi][2]), "=r"(a[mi][3])
                             : "r"(addr));
            }
#pragma unroll
            for (int pq = 0; pq < 2; pq++) {
                uint32_t addr = bbase + pq * 16 * (BSTR * 2) + kk * 32;
                asm volatile("ldmatrix.sync.aligned.m8n8.x4.shared.b16 {%0,%1,%2,%3}, [%4];"
                             : "=r"(b[2 * pq][0]), "=r"(b[2 * pq][1]),
                               "=r"(b[2 * pq + 1][0]), "=r"(b[2 * pq + 1][1])
                             : "r"(addr));
            }
#pragma unroll
            for (int mi = 0; mi < 2; mi++)
#pragma unroll
                for (int nf = 0; nf < 4; nf++)
                    asm volatile(
                        "mma.sync.aligned.m16n8k16.row.col.f32.bf16.bf16.f32 "
                        "{%0,%1,%2,%3}, {%4,%5,%6,%7}, {%8,%9}, {%0,%1,%2,%3};"
                        : "+f"(c[mi][nf][0]), "+f"(c[mi][nf][1]),
                          "+f"(c[mi][nf][2]), "+f"(c[mi][nf][3])
                        : "r"(a[mi][0]), "r"(a[mi][1]), "r"(a[mi][2]), "r"(a[mi][3]),
                          "r"(b[nf][0]), "r"(b[nf][1]));
        }
        __syncthreads();
        if (i + 2 < 32) ISSUE_B(i + 2, buf)
        asm volatile("cp.async.commit_group;" ::: "memory");

        if (kt == 7) {
            // epilogue for e-tile et = i>>3: corr += C .* delta; reset C
            const int et = i >> 3;
#pragma unroll
            for (int mi = 0; mi < 2; mi++) {
                int r0 = wm * 32 + mi * 16 + gid;
#pragma unroll
                for (int nf = 0; nf < 4; nf++) {
                    int e = et * 128 + we * 32 + nf * 8 + tig * 2;
                    uint32_t v0 = *(const uint32_t*)(sm + SM_A + r0 * (AS * 2) + e * 2);
                    uint32_t v1 = *(const uint32_t*)(sm + SM_A + (r0 + 8) * (AS * 2) + e * 2);
                    float2 f0 = __bfloat1622float2(*(__nv_bfloat162*)&v0);
                    float2 f1 = __bfloat1622float2(*(__nv_bfloat162*)&v1);
                    p[mi * 2 + 0] += c[mi][nf][0] * f0.x + c[mi][nf][1] * f0.y;
                    p[mi * 2 + 1] += c[mi][nf][2] * f1.x + c[mi][nf][3] * f1.y;
                    c[mi][nf][0] = c[mi][nf][1] = c[mi][nf][2] = c[mi][nf][3] = 0.f;
                }
            }
        }
    }

    // combine the four we-quarters per row
    atomicAdd((float*)(sm + SM_RC + (wm * 32 + gid) * 4),      p[0]);
    atomicAdd((float*)(sm + SM_RC + (wm * 32 + gid + 8) * 4),  p[1]);
    atomicAdd((float*)(sm + SM_RC + (wm * 32 + gid + 16) * 4), p[2]);
    atomicAdd((float*)(sm + SM_RC + (wm * 32 + gid + 24) * 4), p[3]);
    __syncthreads();

    if (tid < MT)
        out[rowbase + tid] = *(const float*)(sm + SM_RSS + tid * 4) +
                             *(const float*)(sm + SM_RC + tid * 4);
}

// ---------------------------------------------------------------------------
extern "C" void kernel_launch(void* const* d_in, const int* in_sizes, int n_in,
                              void* d_out, int out_size) {
    const float* x  = (const float*)d_in[0];
    const float* xf = (const float*)d_in[1];
    const float* S  = (const float*)d_in[2];
    float* out = (float*)d_out;

    cudaFuncSetAttribute(mahal_fused, cudaFuncAttributeMaxDynamicSharedMemorySize, SM_TOTAL);

    prep_R<<<(DIM * DIM) / 256, 256>>>(S);
    mahal_fused<<<N_ROWS / MT, 256, SM_TOTAL>>>(x, xf, out);
}